// round 11
// baseline (speedup 1.0000x reference)
#include <cuda_runtime.h>
#include <cuda_bf16.h>
#include <math.h>
#include <stdint.h>

#define B_      512
#define T_      128
#define V_      36
#define E_      128
#define H_      512
#define TSTEPS  127

#define PROBS_N  ((size_t)B_ * TSTEPS * V_)
#define EMB_N    ((size_t)B_ * T_ * E_)
#define OFF_PROBS 0
#define OFF_EMB   (PROBS_N)
#define OFF_SL    (OFF_EMB + EMB_N)
#define OFF_MEAN  (OFF_SL + B_)

// ---------------- device scratch (no allocation) ----------------
// Weights split bf16 hi/lo. Column interleave: out-col c <-> orig gate row
//   r = ((c>>3)&3)*512 + (c>>5)*8 + (c&7)
__device__ __nv_bfloat16 g_W0h[2048 * 640];
__device__ __nv_bfloat16 g_W0l[2048 * 640];
__device__ __nv_bfloat16 g_W1h[2048 * 1024];
__device__ __nv_bfloat16 g_W1l[2048 * 1024];
__device__ float g_b0i[2048], g_b1i[2048];
__device__ __nv_bfloat16 g_Eh[36 * 128], g_El[36 * 128];
__device__ __nv_bfloat16 g_h0h[2][512 * 512], g_h0l[2][512 * 512];
__device__ __nv_bfloat16 g_h1h[2][512 * 512], g_h1l[2][512 * 512];
__device__ float g_c0[512 * 512], g_c1[512 * 512];
__device__ float g_loss[512 * TSTEPS];

// ---------------- smem layout (bytes) ----------------
// CTA tile 128(M) x 64(N), BK=64. A tiles 128 rows, B tiles 64 rows; stride 72 elems.
#define LDA2     72
#define A_TILE   (128 * LDA2 * 2)            // 18432
#define B_TILE   (64 * LDA2 * 2)             // 9216
#define S_AHI    0
#define S_ALO    (A_TILE)
#define S_BHI    (2 * A_TILE)
#define S_BLO    (2 * A_TILE + B_TILE)
#define STAGE_B  (2 * A_TILE + 2 * B_TILE)   // 55296
#define NSTAGE   2
#define S_TOK    (NSTAGE * STAGE_B)          // 110592
#define SMEM_BYTES (S_TOK + 512)             // 111104

// ---------------- PTX helpers ----------------
__device__ __forceinline__ uint32_t smem_u32(const void* p) {
    uint32_t a;
    asm("{ .reg .u64 t; cvta.to.shared.u64 t, %1; cvt.u32.u64 %0, t; }" : "=r"(a) : "l"(p));
    return a;
}
__device__ __forceinline__ void cp16(uint32_t dst, const void* src) {
    asm volatile("cp.async.cg.shared.global [%0], [%1], 16;" :: "r"(dst), "l"(src));
}
__device__ __forceinline__ void cp_commit() { asm volatile("cp.async.commit_group;" ::: "memory"); }
__device__ __forceinline__ void cp_wait0()  { asm volatile("cp.async.wait_group 0;" ::: "memory"); }
__device__ __forceinline__ void cp_wait1()  { asm volatile("cp.async.wait_group 1;" ::: "memory"); }
__device__ __forceinline__ void ldsm_x4(uint32_t* r, uint32_t addr) {
    asm volatile("ldmatrix.sync.aligned.m8n8.x4.shared.b16 {%0,%1,%2,%3}, [%4];"
                 : "=r"(r[0]), "=r"(r[1]), "=r"(r[2]), "=r"(r[3]) : "r"(addr));
}
__device__ __forceinline__ void mma16816(float* d, const uint32_t* a, const uint32_t* b) {
    asm volatile(
        "mma.sync.aligned.m16n8k16.row.col.f32.bf16.bf16.f32 "
        "{%0,%1,%2,%3}, {%4,%5,%6,%7}, {%8,%9}, {%0,%1,%2,%3};"
        : "+f"(d[0]), "+f"(d[1]), "+f"(d[2]), "+f"(d[3])
        : "r"(a[0]), "r"(a[1]), "r"(a[2]), "r"(a[3]), "r"(b[0]), "r"(b[1]));
}

// ---------------- GEMM + fused LSTM cell (256 thr, 8 warps 4x2, warp tile 32x32, BK=64) ----
// CTA tile 128x64. tileid: m0 = (tileid>>5)*128, col0 = (tileid&31)*64. 128 CTAs per gemm.
// which==0: step s: A = [emb(x[:,s]) | h0[par_prev]], K=640,  writes h0[par_cur], c0
// which==1: step s: A = [h0[par_cur] | h1[par_prev]], K=1024, writes h1[par_cur], c1
__device__ void gemm_part(char* sm, int tileid, int which, int s, const int* __restrict__ x) {
    const int tid = threadIdx.x;
    const int m0 = (tileid >> 5) * 128;
    const int col0 = (tileid & 31) * 64;
    const int K = which ? 1024 : 640;
    const int nch = K / 64;
    const int par_cur = s & 1, par_prev = (s + 1) & 1;
    const uint32_t sb = smem_u32(sm);

    int* tok_s = (int*)(sm + S_TOK);
    if (which == 0 && tid < 128) tok_s[tid] = x[(m0 + tid) * T_ + s];
    __syncthreads();

    const __nv_bfloat16* __restrict__ Wh = which ? g_W1h : g_W0h;
    const __nv_bfloat16* __restrict__ Wl = which ? g_W1l : g_W0l;

    const int warp = tid >> 5, lane = tid & 31;
    const int wm = warp >> 1, wn = warp & 1;      // wm 0..3 (32-row bands), wn 0..1 (32-col bands)

    // loader: 256 threads cover 32 rows x 64 k per pass
    const int ldr = (tid >> 3);          // 0..31
    const int ldk = (tid & 7) * 8;       // 0..56

    auto load_chunk = [&](int c, int buf) {
        const int kb = c * 64;
        const uint32_t sbst = sb + buf * STAGE_B;
        // A: 128 rows (4 passes)
#pragma unroll
        for (int it = 0; it < 4; it++) {
            const int r = it * 32 + ldr;
            const int kk = kb + ldk;
            const __nv_bfloat16 *pah, *pal;
            if (which) {
                if (kb < 512) {
                    size_t o = (size_t)(m0 + r) * 512 + kk;
                    pah = &g_h0h[par_cur][o]; pal = &g_h0l[par_cur][o];
                } else {
                    size_t o = (size_t)(m0 + r) * 512 + kk - 512;
                    pah = &g_h1h[par_prev][o]; pal = &g_h1l[par_prev][o];
                }
            } else {
                if (kb < 128) {
                    size_t o = (size_t)tok_s[r] * 128 + kk;
                    pah = &g_Eh[o]; pal = &g_El[o];
                } else {
                    size_t o = (size_t)(m0 + r) * 512 + kk - 128;
                    pah = &g_h0h[par_prev][o]; pal = &g_h0l[par_prev][o];
                }
            }
            const int dst = (r * LDA2 + ldk) * 2;
            cp16(sbst + S_AHI + dst, pah);
            cp16(sbst + S_ALO + dst, pal);
        }
        // B: 64 rows (2 passes)
#pragma unroll
        for (int it = 0; it < 2; it++) {
            const int r = it * 32 + ldr;
            const int dst = (r * LDA2 + ldk) * 2;
            size_t bo = (size_t)(col0 + r) * K + kb + ldk;
            cp16(sbst + S_BHI + dst, &Wh[bo]);
            cp16(sbst + S_BLO + dst, &Wl[bo]);
        }
    };

    float acc[2][4][4];
#pragma unroll
    for (int i = 0; i < 2; i++)
#pragma unroll
        for (int q = 0; q < 4; q++)
#pragma unroll
            for (int r = 0; r < 4; r++) acc[i][q][r] = 0.f;

    // ldmatrix per-thread base addresses (stage 0)
    const int arow = wm * 32 + (lane & 15);
    const int ahalf = (lane >> 4) * 8;                 // A: x4 = 2 m-halves x 2 k-halves
    const uint32_t a_hi0 = sb + S_AHI + (arow * LDA2 + ahalf) * 2;
    const uint32_t a_lo0 = sb + S_ALO + (arow * LDA2 + ahalf) * 2;
    const int brow = wn * 32 + (lane & 7);
    const int bhalf = (lane >> 3) * 8;                 // B: x4 = 4 consecutive k-halves
    const uint32_t b_hi0 = sb + S_BHI + (brow * LDA2 + bhalf) * 2;
    const uint32_t b_lo0 = sb + S_BLO + (brow * LDA2 + bhalf) * 2;

    load_chunk(0, 0); cp_commit();

    int buf = 0;
    for (int c = 0; c < nch; c++) {
        if (c + 1 < nch) {
            load_chunk(c + 1, buf ^ 1);
            cp_commit();
            cp_wait1();
        } else {
            cp_wait0();
        }
        __syncthreads();
        const uint32_t so = (uint32_t)(buf * STAGE_B);
#pragma unroll
        for (int kh = 0; kh < 2; kh++) {
            const uint32_t koff = so + (uint32_t)(kh * 32 * 2);   // 32 k-elements per half
            uint32_t bh[4][4], bl[4][4], afh[2][2][4], afl[2][2][4];
            // load B-hi + A-hi fragments
#pragma unroll
            for (int q = 0; q < 4; q++)
                ldsm_x4(bh[q], b_hi0 + koff + q * (8 * LDA2 * 2));
#pragma unroll
            for (int ks = 0; ks < 2; ks++)
#pragma unroll
                for (int mf = 0; mf < 2; mf++)
                    ldsm_x4(afh[ks][mf], a_hi0 + koff + ks * 32 + mf * (16 * LDA2 * 2));
            // pass 1: hi*hi  (8 independent acc chains per ks)
#pragma unroll
            for (int ks = 0; ks < 2; ks++)
#pragma unroll
                for (int mf = 0; mf < 2; mf++)
#pragma unroll
                    for (int q = 0; q < 4; q++)
                        mma16816(acc[mf][q], afh[ks][mf], &bh[q][ks * 2]);
            // load B-lo; pass 2: hi*lo
#pragma unroll
            for (int q = 0; q < 4; q++)
                ldsm_x4(bl[q], b_lo0 + koff + q * (8 * LDA2 * 2));
#pragma unroll
            for (int ks = 0; ks < 2; ks++)
#pragma unroll
                for (int mf = 0; mf < 2; mf++)
#pragma unroll
                    for (int q = 0; q < 4; q++)
                        mma16816(acc[mf][q], afh[ks][mf], &bl[q][ks * 2]);
            // load A-lo; pass 3: lo*hi
#pragma unroll
            for (int ks = 0; ks < 2; ks++)
#pragma unroll
                for (int mf = 0; mf < 2; mf++)
                    ldsm_x4(afl[ks][mf], a_lo0 + koff + ks * 32 + mf * (16 * LDA2 * 2));
#pragma unroll
            for (int ks = 0; ks < 2; ks++)
#pragma unroll
                for (int mf = 0; mf < 2; mf++)
#pragma unroll
                    for (int q = 0; q < 4; q++)
                        mma16816(acc[mf][q], afl[ks][mf], &bh[q][ks * 2]);
        }
        __syncthreads();
        buf ^= 1;
    }

    // ---- fused LSTM cell epilogue ----
    const float* __restrict__ bias = which ? g_b1i : g_b0i;
    float* __restrict__ Cc = which ? g_c1 : g_c0;
    __nv_bfloat16* __restrict__ Hh = which ? g_h1h[par_cur] : g_h0h[par_cur];
    __nv_bfloat16* __restrict__ Hl = which ? g_h1l[par_cur] : g_h0l[par_cur];

    const int p = lane & 3;
    const int rowb = lane >> 2;
    const int jbase = (col0 >> 2) + wn * 8;
    float bi[4][2];
#pragma unroll
    for (int g = 0; g < 4; g++) {
        bi[g][0] = bias[col0 + wn * 32 + g * 8 + 2 * p + 0];
        bi[g][1] = bias[col0 + wn * 32 + g * 8 + 2 * p + 1];
    }

#pragma unroll
    for (int mf = 0; mf < 2; mf++) {
#pragma unroll
        for (int r2 = 0; r2 < 2; r2++) {
            const int m = m0 + wm * 32 + mf * 16 + rowb + r2 * 8;
            const size_t cb = (size_t)m * 512 + jbase + 2 * p;
            float2 cold = *(const float2*)&Cc[cb];
            float hn[2], cn[2];
#pragma unroll
            for (int bit = 0; bit < 2; bit++) {
                const int ri = r2 * 2 + bit;
                float iv = acc[mf][0][ri] + bi[0][bit];
                float fv = acc[mf][1][ri] + bi[1][bit];
                float gv = acc[mf][2][ri] + bi[2][bit];
                float ov = acc[mf][3][ri] + bi[3][bit];
                float si = 1.f / (1.f + expf(-iv));
                float sf = 1.f / (1.f + expf(-fv));
                float tg = tanhf(gv);
                float so = 1.f / (1.f + expf(-ov));
                float co = bit ? cold.y : cold.x;
                cn[bit] = sf * co + si * tg;
                hn[bit] = so * tanhf(cn[bit]);
            }
            *(float2*)&Cc[cb] = make_float2(cn[0], cn[1]);
            __nv_bfloat16 h0b = __float2bfloat16(hn[0]);
            __nv_bfloat16 h1b = __float2bfloat16(hn[1]);
            __nv_bfloat16 l0b = __float2bfloat16(hn[0] - __bfloat162float(h0b));
            __nv_bfloat16 l1b = __float2bfloat16(hn[1] - __bfloat162float(h1b));
            uint32_t hp = (uint32_t)__bfloat16_as_ushort(h0b) |
                          ((uint32_t)__bfloat16_as_ushort(h1b) << 16);
            uint32_t lp = (uint32_t)__bfloat16_as_ushort(l0b) |
                          ((uint32_t)__bfloat16_as_ushort(l1b) << 16);
            *(uint32_t*)&Hh[cb] = hp;
            *(uint32_t*)&Hl[cb] = lp;
        }
    }
}

// ---------------- fc: 8 batches/block, warp w handles batch b0+w (256 thr) ----------------
__device__ void fc_part(char* sm, int fid, int s, const int* __restrict__ x,
                        const float* __restrict__ Wfc, const float* __restrict__ bfc,
                        float* __restrict__ out) {
    const int tid = threadIdx.x;
    float* hs = (float*)sm;               // [8][512]
    float* lgs = (float*)(sm + 16384);    // [8][40]
    const int b0 = fid * 8;
    const int par = s & 1;
    for (int i = tid; i < 8 * 512; i += 256) {
        int b = i >> 9, k = i & 511;
        size_t idx = (size_t)(b0 + b) * 512 + k;
        hs[i] = __bfloat162float(g_h1h[par][idx]) + __bfloat162float(g_h1l[par][idx]);
    }
    __syncthreads();
    const int w = tid >> 5, lane = tid & 31;
    {
        const int b = b0 + w;
        const float* hb = hs + w * 512;
        for (int v = 0; v < V_; v++) {
            float sum = 0.f;
#pragma unroll
            for (int kk = 0; kk < 16; kk++) {
                int k = lane + kk * 32;
                sum += hb[k] * Wfc[v * 512 + k];
            }
#pragma unroll
            for (int o = 16; o; o >>= 1) sum += __shfl_xor_sync(0xffffffffu, sum, o);
            if (lane == 0) lgs[w * 40 + v] = fmaxf(sum + bfc[v], 0.f);
        }
        __syncwarp();
        if (lane == 0) {
            float mx = -1e30f;
            for (int v = 0; v < V_; v++) mx = fmaxf(mx, lgs[w * 40 + v]);
            float se = 0.f;
            for (int v = 0; v < V_; v++) se += expf(lgs[w * 40 + v] - mx);
            lgs[w * 40 + 36] = mx;
            lgs[w * 40 + 37] = se;
            int tgt = x[b * T_ + s + 1];
            g_loss[b * TSTEPS + s] = (tgt == 0) ? 0.f : -lgs[w * 40 + tgt];
        }
        __syncwarp();
        for (int v = lane; v < V_; v += 32) {
            float pr = expf(lgs[w * 40 + v] - lgs[w * 40 + 36]) / lgs[w * 40 + 37];
            out[OFF_PROBS + ((size_t)b * TSTEPS + s) * V_ + v] = pr;
        }
    }
}

// ---------------- step kernel ----------------
// mode 0: gemm0(step 0), grid 128
// mode 1: grid 256 = gemm1(t)[0..127] + [gemm0(t+1) [128..255] + fc(t-1) in blocks 128..191]
// mode 2: fc(126), grid 64
__global__ __launch_bounds__(256, 2) void step_kernel(int t, int mode,
        const int* __restrict__ x, const float* __restrict__ Wfc,
        const float* __restrict__ bfc, float* __restrict__ out) {
    extern __shared__ char sm[];
    int bid = blockIdx.x;
    if (mode == 0) { gemm_part(sm, bid, 0, 0, x); return; }
    if (mode == 2) { fc_part(sm, bid, 126, x, Wfc, bfc, out); return; }
    if (bid < 128) {
        gemm_part(sm, bid, 1, t, x);
    } else {
        if (t < 126) gemm_part(sm, bid - 128, 0, t + 1, x);
        if (t > 0 && bid < 192) {
            __syncthreads();
            fc_part(sm, bid - 128, t - 1, x, Wfc, bfc, out);
        }
    }
}

// ---------------- prologue ----------------
__global__ void prep_kernel(const float* __restrict__ Wih0, const float* __restrict__ Whh0,
                            const float* __restrict__ Wih1, const float* __restrict__ Whh1,
                            const float* __restrict__ bi0, const float* __restrict__ bh0,
                            const float* __restrict__ bi1, const float* __restrict__ bh1,
                            const float* __restrict__ tab) {
    int i = blockIdx.x * 256 + threadIdx.x;
    if (i < 2048 * 1024) {
        int np = i >> 10, k = i & 1023;
        int r = ((np >> 3) & 3) * 512 + (np >> 5) * 8 + (np & 7);
        float v = (k < 512) ? Wih1[r * 512 + k] : Whh1[r * 512 + k - 512];
        __nv_bfloat16 hi = __float2bfloat16(v);
        g_W1h[i] = hi;
        g_W1l[i] = __float2bfloat16(v - __bfloat162float(hi));
    }
    if (i < 2048 * 640) {
        int np = i / 640, k = i - np * 640;
        int r = ((np >> 3) & 3) * 512 + (np >> 5) * 8 + (np & 7);
        float v = (k < 128) ? Wih0[r * 128 + k] : Whh0[r * 512 + k - 128];
        __nv_bfloat16 hi = __float2bfloat16(v);
        g_W0h[i] = hi;
        g_W0l[i] = __float2bfloat16(v - __bfloat162float(hi));
    }
    if (i < 36 * 128) {
        float v = tab[i];
        __nv_bfloat16 hi = __float2bfloat16(v);
        g_Eh[i] = hi;
        g_El[i] = __float2bfloat16(v - __bfloat162float(hi));
    }
    if (i < 2048) {
        int r = ((i >> 3) & 3) * 512 + (i >> 5) * 8 + (i & 7);
        g_b0i[i] = bi0[r] + bh0[r];
        g_b1i[i] = bi1[r] + bh1[r];
    }
    if (i < 512 * 512) {
        g_c0[i] = 0.f; g_c1[i] = 0.f;
        __nv_bfloat16 z = __float2bfloat16(0.f);
        g_h0h[1][i] = z; g_h0l[1][i] = z;
        g_h1h[1][i] = z; g_h1l[1][i] = z;
    }
}

// ---------------- embedding output ----------------
__global__ void embed_kernel(const int* __restrict__ x, const float* __restrict__ tab,
                             float* __restrict__ out_emb) {
    int idx = blockIdx.x * 256 + threadIdx.x;
    if (idx >= (int)(EMB_N / 4)) return;
    int e4 = idx & 31;
    int bt = idx >> 5;
    int tok = x[bt];
    float4 v = reinterpret_cast<const float4*>(tab)[tok * 32 + e4];
    reinterpret_cast<float4*>(out_emb)[idx] = v;
}

// ---------------- finalize ----------------
__global__ void finalize_kernel(const int* __restrict__ x, float* __restrict__ out) {
    __shared__ float red[B_];
    int b = threadIdx.x;
    float s = 0.f;
    for (int t = 0; t < TSTEPS; t++) s += g_loss[b * TSTEPS + t];
    int len = 0;
    for (int t = 0; t < T_; t++) len += (x[b * T_ + t] != 0);
    float sl = s / (float)len;
    out[OFF_SL + b] = sl;
    red[b] = sl;
    __syncthreads();
    for (int st = 256; st > 0; st >>= 1) {
        if (b < st) red[b] += red[b + st];
        __syncthreads();
    }
    if (b == 0) out[OFF_MEAN] = red[0] / (float)B_;
}

// ---------------- launch ----------------
extern "C" void kernel_launch(void* const* d_in, const int* in_sizes, int n_in,
                              void* d_out, int out_size) {
    const int*   x    = (const int*)  d_in[0];
    const float* tab  = (const float*)d_in[1];
    const float* Wih0 = (const float*)d_in[2];
    const float* Whh0 = (const float*)d_in[3];
    const float* bih0 = (const float*)d_in[4];
    const float* bhh0 = (const float*)d_in[5];
    const float* Wih1 = (const float*)d_in[6];
    const float* Whh1 = (const float*)d_in[7];
    const float* bih1 = (const float*)d_in[8];
    const float* bhh1 = (const float*)d_in[9];
    const float* Wfc  = (const float*)d_in[10];
    const float* bfc  = (const float*)d_in[11];
    float* out = (float*)d_out;

    cudaFuncSetAttribute(step_kernel, cudaFuncAttributeMaxDynamicSharedMemorySize, SMEM_BYTES);

    prep_kernel<<<(2048 * 1024) / 256, 256>>>(Wih0, Whh0, Wih1, Whh1,
                                              bih0, bhh0, bih1, bhh1, tab);
    embed_kernel<<<(int)((EMB_N / 4 + 255) / 256), 256>>>(x, tab, out + OFF_EMB);

    step_kernel<<<128, 256, SMEM_BYTES>>>(0, 0, x, Wfc, bfc, out);
    for (int t = 0; t < TSTEPS; t++)
        step_kernel<<<256, 256, SMEM_BYTES>>>(t, 1, x, Wfc, bfc, out);
    step_kernel<<<64, 256, SMEM_BYTES>>>(0, 2, x, Wfc, bfc, out);
    finalize_kernel<<<1, B_>>>(x, out);
}

// round 12
// speedup vs baseline: 1.1260x; 1.1260x over previous
#include <cuda_runtime.h>
#include <cuda_bf16.h>
#include <math.h>
#include <stdint.h>

#define B_      512
#define T_      128
#define V_      36
#define E_      128
#define H_      512
#define TSTEPS  127

#define PROBS_N  ((size_t)B_ * TSTEPS * V_)
#define EMB_N    ((size_t)B_ * T_ * E_)
#define OFF_PROBS 0
#define OFF_EMB   (PROBS_N)
#define OFF_SL    (OFF_EMB + EMB_N)
#define OFF_MEAN  (OFF_SL + B_)

// ---------------- device scratch (no allocation) ----------------
// Weights split bf16 hi/lo. Column interleave: out-col c <-> orig gate row
//   r = ((c>>3)&3)*512 + (c>>5)*8 + (c&7)
__device__ __nv_bfloat16 g_W0h[2048 * 640];
__device__ __nv_bfloat16 g_W0l[2048 * 640];
__device__ __nv_bfloat16 g_W1h[2048 * 1024];
__device__ __nv_bfloat16 g_W1l[2048 * 1024];
__device__ float g_b0i[2048], g_b1i[2048];
__device__ __nv_bfloat16 g_Eh[36 * 128], g_El[36 * 128];
__device__ __nv_bfloat16 g_h0h[2][512 * 512], g_h0l[2][512 * 512];
__device__ __nv_bfloat16 g_h1h[2][512 * 512], g_h1l[2][512 * 512];
__device__ float g_c0[512 * 512], g_c1[512 * 512];
__device__ float g_loss[512 * TSTEPS];

// ---------------- smem layout (bytes) ----------------
// Per stage: 4 tiles [128 rows][64 k] bf16, row stride 72 elems (144B)
#define LDA2     72
#define TILE_B2  (128 * LDA2 * 2)            // 18432
#define S_AHI    0
#define S_ALO    (1 * TILE_B2)
#define S_BHI    (2 * TILE_B2)
#define S_BLO    (3 * TILE_B2)
#define STAGE_B  (4 * TILE_B2)               // 73728
#define NSTAGE   3
#define S_TOK    (NSTAGE * STAGE_B)          // 221184
#define SMEM_BYTES (S_TOK + 512)             // 221696

// ---------------- PTX helpers ----------------
__device__ __forceinline__ uint32_t smem_u32(const void* p) {
    uint32_t a;
    asm("{ .reg .u64 t; cvta.to.shared.u64 t, %1; cvt.u32.u64 %0, t; }" : "=r"(a) : "l"(p));
    return a;
}
__device__ __forceinline__ void cp16(uint32_t dst, const void* src) {
    asm volatile("cp.async.cg.shared.global [%0], [%1], 16;" :: "r"(dst), "l"(src));
}
__device__ __forceinline__ void cp_commit() { asm volatile("cp.async.commit_group;" ::: "memory"); }
__device__ __forceinline__ void cp_wait0()  { asm volatile("cp.async.wait_group 0;" ::: "memory"); }
__device__ __forceinline__ void cp_wait1()  { asm volatile("cp.async.wait_group 1;" ::: "memory"); }
__device__ __forceinline__ void ldsm_x4(uint32_t* r, uint32_t addr) {
    asm volatile("ldmatrix.sync.aligned.m8n8.x4.shared.b16 {%0,%1,%2,%3}, [%4];"
                 : "=r"(r[0]), "=r"(r[1]), "=r"(r[2]), "=r"(r[3]) : "r"(addr));
}
__device__ __forceinline__ void mma16816(float* d, const uint32_t* a, const uint32_t* b) {
    asm volatile(
        "mma.sync.aligned.m16n8k16.row.col.f32.bf16.bf16.f32 "
        "{%0,%1,%2,%3}, {%4,%5,%6,%7}, {%8,%9}, {%0,%1,%2,%3};"
        : "+f"(d[0]), "+f"(d[1]), "+f"(d[2]), "+f"(d[3])
        : "r"(a[0]), "r"(a[1]), "r"(a[2]), "r"(a[3]), "r"(b[0]), "r"(b[1]));
}

// ---------------- GEMM + fused LSTM cell (512 thr, 16 warps 4x4, warp tile 32x32, BK=64) ----
// which==0: step s: A = [emb(x[:,s]) | h0[par_prev]], K=640,  writes h0[par_cur], c0
// which==1: step s: A = [h0[par_cur] | h1[par_prev]], K=1024, writes h1[par_cur], c1
__device__ void gemm_part(char* sm, int tileid, int which, int s, const int* __restrict__ x) {
    const int tid = threadIdx.x;
    const int m0 = (tileid >> 4) * 128;
    const int col0 = (tileid & 15) * 128;
    const int K = which ? 1024 : 640;
    const int nch = K / 64;
    const int par_cur = s & 1, par_prev = (s + 1) & 1;
    const uint32_t sb = smem_u32(sm);

    int* tok_s = (int*)(sm + S_TOK);
    if (which == 0 && tid < 128) tok_s[tid] = x[(m0 + tid) * T_ + s];
    __syncthreads();

    const __nv_bfloat16* __restrict__ Wh = which ? g_W1h : g_W0h;
    const __nv_bfloat16* __restrict__ Wl = which ? g_W1l : g_W0l;

    const int warp = tid >> 5, lane = tid & 31;
    const int wm = warp >> 2, wn = warp & 3;

    // loader: 512 threads cover 64 rows x 64 k per pass; 2 passes = 128 rows
    const int ldr = (tid >> 3);          // 0..63
    const int ldk = (tid & 7) * 8;       // 0..56

    auto load_chunk = [&](int c, int buf) {
        const int kb = c * 64;
        const uint32_t sbst = sb + buf * STAGE_B;
#pragma unroll
        for (int it = 0; it < 2; it++) {
            const int r = it * 64 + ldr;
            const int kk = kb + ldk;
            const __nv_bfloat16 *pah, *pal;
            if (which) {
                if (kb < 512) {
                    size_t o = (size_t)(m0 + r) * 512 + kk;
                    pah = &g_h0h[par_cur][o]; pal = &g_h0l[par_cur][o];
                } else {
                    size_t o = (size_t)(m0 + r) * 512 + kk - 512;
                    pah = &g_h1h[par_prev][o]; pal = &g_h1l[par_prev][o];
                }
            } else {
                if (kb < 128) {
                    size_t o = (size_t)tok_s[r] * 128 + kk;
                    pah = &g_Eh[o]; pal = &g_El[o];
                } else {
                    size_t o = (size_t)(m0 + r) * 512 + kk - 128;
                    pah = &g_h0h[par_prev][o]; pal = &g_h0l[par_prev][o];
                }
            }
            const int dst = (r * LDA2 + ldk) * 2;
            cp16(sbst + S_AHI + dst, pah);
            cp16(sbst + S_ALO + dst, pal);
            size_t bo = (size_t)(col0 + r) * K + kk;
            cp16(sbst + S_BHI + dst, &Wh[bo]);
            cp16(sbst + S_BLO + dst, &Wl[bo]);
        }
    };

    float acc[2][4][4];
#pragma unroll
    for (int i = 0; i < 2; i++)
#pragma unroll
        for (int q = 0; q < 4; q++)
#pragma unroll
            for (int r = 0; r < 4; r++) acc[i][q][r] = 0.f;

    // ldmatrix per-thread base addresses (stage 0)
    const int arow = wm * 32 + (lane & 15);
    const int ahalf = (lane >> 4) * 8;                 // A: x4 = 2 m-halves x 2 k-halves
    const uint32_t a_hi0 = sb + S_AHI + (arow * LDA2 + ahalf) * 2;
    const uint32_t a_lo0 = sb + S_ALO + (arow * LDA2 + ahalf) * 2;
    const int brow = wn * 32 + (lane & 7);
    const int bhalf = (lane >> 3) * 8;                 // B: x4 = 4 consecutive k-halves
    const uint32_t b_hi0 = sb + S_BHI + (brow * LDA2 + bhalf) * 2;
    const uint32_t b_lo0 = sb + S_BLO + (brow * LDA2 + bhalf) * 2;

    // prologue: 2 chunks in flight
    load_chunk(0, 0); cp_commit();
    load_chunk(1, 1); cp_commit();

    int buf = 0;
    for (int c = 0; c < nch; c++) {
        // wait for chunk c to be resident (leave chunk c+1 in flight)
        if (c + 1 < nch) cp_wait1(); else cp_wait0();
        // single barrier: all warps done READING stage (c+2)%NSTAGE (from chunk c-1's
        // compute in the previous iteration) before we overwrite it below.
        __syncthreads();
        if (c + 2 < nch) {
            int nb = buf + 2; if (nb >= NSTAGE) nb -= NSTAGE;
            load_chunk(c + 2, nb);
            cp_commit();
        }
        const uint32_t so = (uint32_t)(buf * STAGE_B);
#pragma unroll
        for (int kh = 0; kh < 2; kh++) {
            const uint32_t koff = so + (uint32_t)(kh * 32 * 2);   // 32 k-elements per half
            uint32_t bh[4][4], bl[4][4], afh[2][2][4], afl[2][2][4];
            // load B-hi + A-hi fragments
#pragma unroll
            for (int q = 0; q < 4; q++)
                ldsm_x4(bh[q], b_hi0 + koff + q * (8 * LDA2 * 2));
#pragma unroll
            for (int ks = 0; ks < 2; ks++)
#pragma unroll
                for (int mf = 0; mf < 2; mf++)
                    ldsm_x4(afh[ks][mf], a_hi0 + koff + ks * 32 + mf * (16 * LDA2 * 2));
            // pass 1: hi*hi  (8 independent acc chains per ks)
#pragma unroll
            for (int ks = 0; ks < 2; ks++)
#pragma unroll
                for (int mf = 0; mf < 2; mf++)
#pragma unroll
                    for (int q = 0; q < 4; q++)
                        mma16816(acc[mf][q], afh[ks][mf], &bh[q][ks * 2]);
            // load B-lo; pass 2: hi*lo
#pragma unroll
            for (int q = 0; q < 4; q++)
                ldsm_x4(bl[q], b_lo0 + koff + q * (8 * LDA2 * 2));
#pragma unroll
            for (int ks = 0; ks < 2; ks++)
#pragma unroll
                for (int mf = 0; mf < 2; mf++)
#pragma unroll
                    for (int q = 0; q < 4; q++)
                        mma16816(acc[mf][q], afh[ks][mf], &bl[q][ks * 2]);
            // load A-lo; pass 3: lo*hi
#pragma unroll
            for (int ks = 0; ks < 2; ks++)
#pragma unroll
                for (int mf = 0; mf < 2; mf++)
                    ldsm_x4(afl[ks][mf], a_lo0 + koff + ks * 32 + mf * (16 * LDA2 * 2));
#pragma unroll
            for (int ks = 0; ks < 2; ks++)
#pragma unroll
                for (int mf = 0; mf < 2; mf++)
#pragma unroll
                    for (int q = 0; q < 4; q++)
                        mma16816(acc[mf][q], afl[ks][mf], &bh[q][ks * 2]);
        }
        if (++buf == NSTAGE) buf = 0;
    }

    // ---- fused LSTM cell epilogue ----
    const float* __restrict__ bias = which ? g_b1i : g_b0i;
    float* __restrict__ Cc = which ? g_c1 : g_c0;
    __nv_bfloat16* __restrict__ Hh = which ? g_h1h[par_cur] : g_h0h[par_cur];
    __nv_bfloat16* __restrict__ Hl = which ? g_h1l[par_cur] : g_h0l[par_cur];

    const int p = lane & 3;
    const int rowb = lane >> 2;
    const int jbase = (col0 >> 2) + wn * 8;
    float bi[4][2];
#pragma unroll
    for (int g = 0; g < 4; g++) {
        bi[g][0] = bias[col0 + wn * 32 + g * 8 + 2 * p + 0];
        bi[g][1] = bias[col0 + wn * 32 + g * 8 + 2 * p + 1];
    }

#pragma unroll
    for (int mf = 0; mf < 2; mf++) {
#pragma unroll
        for (int r2 = 0; r2 < 2; r2++) {
            const int m = m0 + wm * 32 + mf * 16 + rowb + r2 * 8;
            const size_t cb = (size_t)m * 512 + jbase + 2 * p;
            float2 cold = *(const float2*)&Cc[cb];
            float hn[2], cn[2];
#pragma unroll
            for (int bit = 0; bit < 2; bit++) {
                const int ri = r2 * 2 + bit;
                float iv = acc[mf][0][ri] + bi[0][bit];
                float fv = acc[mf][1][ri] + bi[1][bit];
                float gv = acc[mf][2][ri] + bi[2][bit];
                float ov = acc[mf][3][ri] + bi[3][bit];
                float si = 1.f / (1.f + expf(-iv));
                float sf = 1.f / (1.f + expf(-fv));
                float tg = tanhf(gv);
                float so = 1.f / (1.f + expf(-ov));
                float co = bit ? cold.y : cold.x;
                cn[bit] = sf * co + si * tg;
                hn[bit] = so * tanhf(cn[bit]);
            }
            *(float2*)&Cc[cb] = make_float2(cn[0], cn[1]);
            __nv_bfloat16 h0b = __float2bfloat16(hn[0]);
            __nv_bfloat16 h1b = __float2bfloat16(hn[1]);
            __nv_bfloat16 l0b = __float2bfloat16(hn[0] - __bfloat162float(h0b));
            __nv_bfloat16 l1b = __float2bfloat16(hn[1] - __bfloat162float(h1b));
            uint32_t hp = (uint32_t)__bfloat16_as_ushort(h0b) |
                          ((uint32_t)__bfloat16_as_ushort(h1b) << 16);
            uint32_t lp = (uint32_t)__bfloat16_as_ushort(l0b) |
                          ((uint32_t)__bfloat16_as_ushort(l1b) << 16);
            *(uint32_t*)&Hh[cb] = hp;
            *(uint32_t*)&Hl[cb] = lp;
        }
    }
}

// ---------------- fc: 8 batches/block, warp w<8 handles batch b0+w ----------------
__device__ void fc_part(char* sm, int fid, int s, const int* __restrict__ x,
                        const float* __restrict__ Wfc, const float* __restrict__ bfc,
                        float* __restrict__ out) {
    const int tid = threadIdx.x;
    float* hs = (float*)sm;               // [8][512]
    float* lgs = (float*)(sm + 16384);    // [8][40]
    const int b0 = fid * 8;
    const int par = s & 1;
    for (int i = tid; i < 8 * 512; i += 512) {
        int b = i >> 9, k = i & 511;
        size_t idx = (size_t)(b0 + b) * 512 + k;
        hs[i] = __bfloat162float(g_h1h[par][idx]) + __bfloat162float(g_h1l[par][idx]);
    }
    __syncthreads();
    const int w = tid >> 5, lane = tid & 31;
    if (w < 8) {
        const int b = b0 + w;
        const float* hb = hs + w * 512;
        for (int v = 0; v < V_; v++) {
            float sum = 0.f;
#pragma unroll
            for (int kk = 0; kk < 16; kk++) {
                int k = lane + kk * 32;
                sum += hb[k] * Wfc[v * 512 + k];
            }
#pragma unroll
            for (int o = 16; o; o >>= 1) sum += __shfl_xor_sync(0xffffffffu, sum, o);
            if (lane == 0) lgs[w * 40 + v] = fmaxf(sum + bfc[v], 0.f);
        }
        __syncwarp();
        if (lane == 0) {
            float mx = -1e30f;
            for (int v = 0; v < V_; v++) mx = fmaxf(mx, lgs[w * 40 + v]);
            float se = 0.f;
            for (int v = 0; v < V_; v++) se += expf(lgs[w * 40 + v] - mx);
            lgs[w * 40 + 36] = mx;
            lgs[w * 40 + 37] = se;
            int tgt = x[b * T_ + s + 1];
            g_loss[b * TSTEPS + s] = (tgt == 0) ? 0.f : -lgs[w * 40 + tgt];
        }
        __syncwarp();
        for (int v = lane; v < V_; v += 32) {
            float pr = expf(lgs[w * 40 + v] - lgs[w * 40 + 36]) / lgs[w * 40 + 37];
            out[OFF_PROBS + ((size_t)b * TSTEPS + s) * V_ + v] = pr;
        }
    }
}

// ---------------- step kernel ----------------
// mode 0: gemm0(step 0), grid 64
// mode 1: grid 128 = gemm1(t)[0..63] + [gemm0(t+1) then fc(t-1)][64..127]
// mode 2: fc(126), grid 64
__global__ __launch_bounds__(512, 1) void step_kernel(int t, int mode,
        const int* __restrict__ x, const float* __restrict__ Wfc,
        const float* __restrict__ bfc, float* __restrict__ out) {
    extern __shared__ char sm[];
    int bid = blockIdx.x;
    if (mode == 0) { gemm_part(sm, bid, 0, 0, x); return; }
    if (mode == 2) { fc_part(sm, bid, 126, x, Wfc, bfc, out); return; }
    if (bid < 64) {
        gemm_part(sm, bid, 1, t, x);
    } else {
        if (t < 126) gemm_part(sm, bid - 64, 0, t + 1, x);
        if (t > 0) {
            __syncthreads();
            fc_part(sm, bid - 64, t - 1, x, Wfc, bfc, out);
        }
    }
}

// ---------------- prologue ----------------
__global__ void prep_kernel(const float* __restrict__ Wih0, const float* __restrict__ Whh0,
                            const float* __restrict__ Wih1, const float* __restrict__ Whh1,
                            const float* __restrict__ bi0, const float* __restrict__ bh0,
                            const float* __restrict__ bi1, const float* __restrict__ bh1,
                            const float* __restrict__ tab) {
    int i = blockIdx.x * 256 + threadIdx.x;
    if (i < 2048 * 1024) {
        int np = i >> 10, k = i & 1023;
        int r = ((np >> 3) & 3) * 512 + (np >> 5) * 8 + (np & 7);
        float v = (k < 512) ? Wih1[r * 512 + k] : Whh1[r * 512 + k - 512];
        __nv_bfloat16 hi = __float2bfloat16(v);
        g_W1h[i] = hi;
        g_W1l[i] = __float2bfloat16(v - __bfloat162float(hi));
    }
    if (i < 2048 * 640) {
        int np = i / 640, k = i - np * 640;
        int r = ((np >> 3) & 3) * 512 + (np >> 5) * 8 + (np & 7);
        float v = (k < 128) ? Wih0[r * 128 + k] : Whh0[r * 512 + k - 128];
        __nv_bfloat16 hi = __float2bfloat16(v);
        g_W0h[i] = hi;
        g_W0l[i] = __float2bfloat16(v - __bfloat162float(hi));
    }
    if (i < 36 * 128) {
        float v = tab[i];
        __nv_bfloat16 hi = __float2bfloat16(v);
        g_Eh[i] = hi;
        g_El[i] = __float2bfloat16(v - __bfloat162float(hi));
    }
    if (i < 2048) {
        int r = ((i >> 3) & 3) * 512 + (i >> 5) * 8 + (i & 7);
        g_b0i[i] = bi0[r] + bh0[r];
        g_b1i[i] = bi1[r] + bh1[r];
    }
    if (i < 512 * 512) {
        g_c0[i] = 0.f; g_c1[i] = 0.f;
        __nv_bfloat16 z = __float2bfloat16(0.f);
        g_h0h[1][i] = z; g_h0l[1][i] = z;
        g_h1h[1][i] = z; g_h1l[1][i] = z;
    }
}

// ---------------- embedding output ----------------
__global__ void embed_kernel(const int* __restrict__ x, const float* __restrict__ tab,
                             float* __restrict__ out_emb) {
    int idx = blockIdx.x * 256 + threadIdx.x;
    if (idx >= (int)(EMB_N / 4)) return;
    int e4 = idx & 31;
    int bt = idx >> 5;
    int tok = x[bt];
    float4 v = reinterpret_cast<const float4*>(tab)[tok * 32 + e4];
    reinterpret_cast<float4*>(out_emb)[idx] = v;
}

// ---------------- finalize ----------------
__global__ void finalize_kernel(const int* __restrict__ x, float* __restrict__ out) {
    __shared__ float red[B_];
    int b = threadIdx.x;
    float s = 0.f;
    for (int t = 0; t < TSTEPS; t++) s += g_loss[b * TSTEPS + t];
    int len = 0;
    for (int t = 0; t < T_; t++) len += (x[b * T_ + t] != 0);
    float sl = s / (float)len;
    out[OFF_SL + b] = sl;
    red[b] = sl;
    __syncthreads();
    for (int st = 256; st > 0; st >>= 1) {
        if (b < st) red[b] += red[b + st];
        __syncthreads();
    }
    if (b == 0) out[OFF_MEAN] = red[0] / (float)B_;
}

// ---------------- launch ----------------
extern "C" void kernel_launch(void* const* d_in, const int* in_sizes, int n_in,
                              void* d_out, int out_size) {
    const int*   x    = (const int*)  d_in[0];
    const float* tab  = (const float*)d_in[1];
    const float* Wih0 = (const float*)d_in[2];
    const float* Whh0 = (const float*)d_in[3];
    const float* bih0 = (const float*)d_in[4];
    const float* bhh0 = (const float*)d_in[5];
    const float* Wih1 = (const float*)d_in[6];
    const float* Whh1 = (const float*)d_in[7];
    const float* bih1 = (const float*)d_in[8];
    const float* bhh1 = (const float*)d_in[9];
    const float* Wfc  = (const float*)d_in[10];
    const float* bfc  = (const float*)d_in[11];
    float* out = (float*)d_out;

    cudaFuncSetAttribute(step_kernel, cudaFuncAttributeMaxDynamicSharedMemorySize, SMEM_BYTES);

    prep_kernel<<<(2048 * 1024) / 256, 256>>>(Wih0, Whh0, Wih1, Whh1,
                                              bih0, bhh0, bih1, bhh1, tab);
    embed_kernel<<<(int)((EMB_N / 4 + 255) / 256), 256>>>(x, tab, out + OFF_EMB);

    step_kernel<<<64, 512, SMEM_BYTES>>>(0, 0, x, Wfc, bfc, out);
    for (int t = 0; t < TSTEPS; t++)
        step_kernel<<<128, 512, SMEM_BYTES>>>(t, 1, x, Wfc, bfc, out);
    step_kernel<<<64, 512, SMEM_BYTES>>>(0, 2, x, Wfc, bfc, out);
    finalize_kernel<<<1, B_>>>(x, out);
}

// round 15
// speedup vs baseline: 1.3036x; 1.1577x over previous
#include <cuda_runtime.h>
#include <cuda_fp16.h>
#include <math.h>
#include <stdint.h>

#define B_      512
#define T_      128
#define V_      36
#define E_      128
#define H_      512
#define TSTEPS  127

#define PROBS_N  ((size_t)B_ * TSTEPS * V_)
#define EMB_N    ((size_t)B_ * T_ * E_)
#define OFF_PROBS 0
#define OFF_EMB   (PROBS_N)
#define OFF_SL    (OFF_EMB + EMB_N)
#define OFF_MEAN  (OFF_SL + B_)

// ---------------- device scratch (no allocation) ----------------
// Weights: single fp16, gate-interleaved columns. out-col c <-> orig gate row
//   r = ((c>>3)&3)*512 + (c>>5)*8 + (c&7)
__device__ __half g_W0[2048 * 640];
__device__ __half g_W1[2048 * 1024];
__device__ float g_b0i[2048], g_b1i[2048];
__device__ __half g_Eh[36 * 128], g_El[36 * 128];       // emb split fp16 hi/lo
__device__ __half g_h0h[2][512 * 512], g_h0l[2][512 * 512];
__device__ __half g_h1h[2][512 * 512], g_h1l[2][512 * 512];
__device__ float g_c0[512 * 512], g_c1[512 * 512];
__device__ float g_loss[512 * TSTEPS];

// ---------------- smem layout (bytes) ----------------
// Per stage: 3 tiles [128 rows][64 k] fp16 (A-hi, A-lo, B), row stride 72 elems
#define LDA2     72
#define TILE_B2  (128 * LDA2 * 2)            // 18432
#define S_AHI    0
#define S_ALO    (1 * TILE_B2)
#define S_B      (2 * TILE_B2)
#define STAGE_B  (3 * TILE_B2)               // 55296
#define NSTAGE   3
#define S_TOK    (NSTAGE * STAGE_B)          // 165888
#define SMEM_BYTES (S_TOK + 512)             // 166400

// ---------------- PTX helpers ----------------
__device__ __forceinline__ uint32_t smem_u32(const void* p) {
    uint32_t a;
    asm("{ .reg .u64 t; cvta.to.shared.u64 t, %1; cvt.u32.u64 %0, t; }" : "=r"(a) : "l"(p));
    return a;
}
__device__ __forceinline__ void cp16(uint32_t dst, const void* src) {
    asm volatile("cp.async.cg.shared.global [%0], [%1], 16;" :: "r"(dst), "l"(src));
}
__device__ __forceinline__ void cp_commit() { asm volatile("cp.async.commit_group;" ::: "memory"); }
__device__ __forceinline__ void cp_wait0()  { asm volatile("cp.async.wait_group 0;" ::: "memory"); }
__device__ __forceinline__ void cp_wait1()  { asm volatile("cp.async.wait_group 1;" ::: "memory"); }
__device__ __forceinline__ void ldsm_x4(uint32_t* r, uint32_t addr) {
    asm volatile("ldmatrix.sync.aligned.m8n8.x4.shared.b16 {%0,%1,%2,%3}, [%4];"
                 : "=r"(r[0]), "=r"(r[1]), "=r"(r[2]), "=r"(r[3]) : "r"(addr));
}
__device__ __forceinline__ void mma16816(float* d, const uint32_t* a, const uint32_t* b) {
    asm volatile(
        "mma.sync.aligned.m16n8k16.row.col.f32.f16.f16.f32 "
        "{%0,%1,%2,%3}, {%4,%5,%6,%7}, {%8,%9}, {%0,%1,%2,%3};"
        : "+f"(d[0]), "+f"(d[1]), "+f"(d[2]), "+f"(d[3])
        : "r"(a[0]), "r"(a[1]), "r"(a[2]), "r"(a[3]), "r"(b[0]), "r"(b[1]));
}

// ---------------- GEMM + fused LSTM cell (512 thr, 16 warps 4x4, warp tile 32x32, BK=64) ----
// which==0: step s: A = [emb(x[:,s]) | h0[par_prev]], K=640,  writes h0[par_cur], c0
// which==1: step s: A = [h0[par_cur] | h1[par_prev]], K=1024, writes h1[par_cur], c1
__device__ void gemm_part(char* sm, int tileid, int which, int s, const int* __restrict__ x) {
    const int tid = threadIdx.x;
    const int m0 = (tileid >> 4) * 128;
    const int col0 = (tileid & 15) * 128;
    const int K = which ? 1024 : 640;
    const int nch = K / 64;
    const int par_cur = s & 1, par_prev = (s + 1) & 1;
    const uint32_t sb = smem_u32(sm);

    int* tok_s = (int*)(sm + S_TOK);
    if (which == 0 && tid < 128) tok_s[tid] = x[(m0 + tid) * T_ + s];
    __syncthreads();

    const __half* __restrict__ W = which ? g_W1 : g_W0;

    const int warp = tid >> 5, lane = tid & 31;
    const int wm = warp >> 2, wn = warp & 3;

    // loader: 512 threads cover 64 rows x 64 k per pass; 2 passes = 128 rows
    const int ldr = (tid >> 3);          // 0..63
    const int ldk = (tid & 7) * 8;       // 0..56

    auto load_chunk = [&](int c, int buf) {
        const int kb = c * 64;
        const uint32_t sbst = sb + buf * STAGE_B;
#pragma unroll
        for (int it = 0; it < 2; it++) {
            const int r = it * 64 + ldr;
            const int kk = kb + ldk;
            const __half *pah, *pal;
            if (which) {
                if (kb < 512) {
                    size_t o = (size_t)(m0 + r) * 512 + kk;
                    pah = &g_h0h[par_cur][o]; pal = &g_h0l[par_cur][o];
                } else {
                    size_t o = (size_t)(m0 + r) * 512 + kk - 512;
                    pah = &g_h1h[par_prev][o]; pal = &g_h1l[par_prev][o];
                }
            } else {
                if (kb < 128) {
                    size_t o = (size_t)tok_s[r] * 128 + kk;
                    pah = &g_Eh[o]; pal = &g_El[o];
                } else {
                    size_t o = (size_t)(m0 + r) * 512 + kk - 128;
                    pah = &g_h0h[par_prev][o]; pal = &g_h0l[par_prev][o];
                }
            }
            const int dst = (r * LDA2 + ldk) * 2;
            cp16(sbst + S_AHI + dst, pah);
            cp16(sbst + S_ALO + dst, pal);
            size_t bo = (size_t)(col0 + r) * K + kk;
            cp16(sbst + S_B + dst, &W[bo]);
        }
    };

    float acc[2][4][4];
#pragma unroll
    for (int i = 0; i < 2; i++)
#pragma unroll
        for (int q = 0; q < 4; q++)
#pragma unroll
            for (int r = 0; r < 4; r++) acc[i][q][r] = 0.f;

    // ldmatrix per-thread base addresses (stage 0)
    const int arow = wm * 32 + (lane & 15);
    const int ahalf = (lane >> 4) * 8;                 // A: x4 = 2 m-halves x 2 k-halves
    const uint32_t a_hi0 = sb + S_AHI + (arow * LDA2 + ahalf) * 2;
    const uint32_t a_lo0 = sb + S_ALO + (arow * LDA2 + ahalf) * 2;
    const int brow = wn * 32 + (lane & 7);
    const int bhalf = (lane >> 3) * 8;                 // B: x4 = 4 consecutive k-halves
    const uint32_t b_0 = sb + S_B + (brow * LDA2 + bhalf) * 2;

    // prologue: 2 chunks in flight
    load_chunk(0, 0); cp_commit();
    load_chunk(1, 1); cp_commit();

    int buf = 0;
    for (int c = 0; c < nch; c++) {
        if (c + 1 < nch) cp_wait1(); else cp_wait0();
        // single barrier: all warps done READING stage (c+2)%NSTAGE before overwrite
        __syncthreads();
        if (c + 2 < nch) {
            int nb = buf + 2; if (nb >= NSTAGE) nb -= NSTAGE;
            load_chunk(c + 2, nb);
            cp_commit();
        }
        const uint32_t so = (uint32_t)(buf * STAGE_B);
#pragma unroll
        for (int kh = 0; kh < 2; kh++) {
            const uint32_t koff = so + (uint32_t)(kh * 32 * 2);   // 32 k-elements per half
            uint32_t bfr[4][4], afh[2][2][4], afl[2][2][4];
            // load B + A-hi fragments
#pragma unroll
            for (int q = 0; q < 4; q++)
                ldsm_x4(bfr[q], b_0 + koff + q * (8 * LDA2 * 2));
#pragma unroll
            for (int ks = 0; ks < 2; ks++)
#pragma unroll
                for (int mf = 0; mf < 2; mf++)
                    ldsm_x4(afh[ks][mf], a_hi0 + koff + ks * 32 + mf * (16 * LDA2 * 2));
            // pass 1: ah * b  (8 independent acc chains per ks)
#pragma unroll
            for (int ks = 0; ks < 2; ks++)
#pragma unroll
                for (int mf = 0; mf < 2; mf++)
#pragma unroll
                    for (int q = 0; q < 4; q++)
                        mma16816(acc[mf][q], afh[ks][mf], &bfr[q][ks * 2]);
            // load A-lo; pass 2: al * b
#pragma unroll
            for (int ks = 0; ks < 2; ks++)
#pragma unroll
                for (int mf = 0; mf < 2; mf++)
                    ldsm_x4(afl[ks][mf], a_lo0 + koff + ks * 32 + mf * (16 * LDA2 * 2));
#pragma unroll
            for (int ks = 0; ks < 2; ks++)
#pragma unroll
                for (int mf = 0; mf < 2; mf++)
#pragma unroll
                    for (int q = 0; q < 4; q++)
                        mma16816(acc[mf][q], afl[ks][mf], &bfr[q][ks * 2]);
        }
        if (++buf == NSTAGE) buf = 0;
    }

    // ---- fused LSTM cell epilogue ----
    const float* __restrict__ bias = which ? g_b1i : g_b0i;
    float* __restrict__ Cc = which ? g_c1 : g_c0;
    __half* __restrict__ Hh = which ? g_h1h[par_cur] : g_h0h[par_cur];
    __half* __restrict__ Hl = which ? g_h1l[par_cur] : g_h0l[par_cur];

    const int p = lane & 3;
    const int rowb = lane >> 2;
    const int jbase = (col0 >> 2) + wn * 8;
    float bi[4][2];
#pragma unroll
    for (int g = 0; g < 4; g++) {
        bi[g][0] = bias[col0 + wn * 32 + g * 8 + 2 * p + 0];
        bi[g][1] = bias[col0 + wn * 32 + g * 8 + 2 * p + 1];
    }

#pragma unroll
    for (int mf = 0; mf < 2; mf++) {
#pragma unroll
        for (int r2 = 0; r2 < 2; r2++) {
            const int m = m0 + wm * 32 + mf * 16 + rowb + r2 * 8;
            const size_t cb = (size_t)m * 512 + jbase + 2 * p;
            float2 cold = *(const float2*)&Cc[cb];
            float hn[2], cn[2];
#pragma unroll
            for (int bit = 0; bit < 2; bit++) {
                const int ri = r2 * 2 + bit;
                float iv = acc[mf][0][ri] + bi[0][bit];
                float fv = acc[mf][1][ri] + bi[1][bit];
                float gv = acc[mf][2][ri] + bi[2][bit];
                float ov = acc[mf][3][ri] + bi[3][bit];
                float si = 1.f / (1.f + expf(-iv));
                float sf = 1.f / (1.f + expf(-fv));
                float tg = tanhf(gv);
                float so = 1.f / (1.f + expf(-ov));
                float co = bit ? cold.y : cold.x;
                cn[bit] = sf * co + si * tg;
                hn[bit] = so * tanhf(cn[bit]);
            }
            *(float2*)&Cc[cb] = make_float2(cn[0], cn[1]);
            __half h0b = __float2half(hn[0]);
            __half h1b = __float2half(hn[1]);
            __half l0b = __float2half(hn[0] - __half2float(h0b));
            __half l1b = __float2half(hn[1] - __half2float(h1b));
            uint32_t hp = (uint32_t)__half_as_ushort(h0b) |
                          ((uint32_t)__half_as_ushort(h1b) << 16);
            uint32_t lp = (uint32_t)__half_as_ushort(l0b) |
                          ((uint32_t)__half_as_ushort(l1b) << 16);
            *(uint32_t*)&Hh[cb] = hp;
            *(uint32_t*)&Hl[cb] = lp;
        }
    }
}

// ---------------- fc: 8 batches/block, warp w<8 handles batch b0+w ----------------
__device__ void fc_part(char* sm, int fid, int s, const int* __restrict__ x,
                        const float* __restrict__ Wfc, const float* __restrict__ bfc,
                        float* __restrict__ out) {
    const int tid = threadIdx.x;
    float* hs = (float*)sm;               // [8][512]
    float* lgs = (float*)(sm + 16384);    // [8][40]
    const int b0 = fid * 8;
    const int par = s & 1;
    for (int i = tid; i < 8 * 512; i += 512) {
        int b = i >> 9, k = i & 511;
        size_t idx = (size_t)(b0 + b) * 512 + k;
        hs[i] = __half2float(g_h1h[par][idx]) + __half2float(g_h1l[par][idx]);
    }
    __syncthreads();
    const int w = tid >> 5, lane = tid & 31;
    if (w < 8) {
        const int b = b0 + w;
        const float* hb = hs + w * 512;
        for (int v = 0; v < V_; v++) {
            float sum = 0.f;
#pragma unroll
            for (int kk = 0; kk < 16; kk++) {
                int k = lane + kk * 32;
                sum += hb[k] * Wfc[v * 512 + k];
            }
#pragma unroll
            for (int o = 16; o; o >>= 1) sum += __shfl_xor_sync(0xffffffffu, sum, o);
            if (lane == 0) lgs[w * 40 + v] = fmaxf(sum + bfc[v], 0.f);
        }
        __syncwarp();
        if (lane == 0) {
            float mx = -1e30f;
            for (int v = 0; v < V_; v++) mx = fmaxf(mx, lgs[w * 40 + v]);
            float se = 0.f;
            for (int v = 0; v < V_; v++) se += expf(lgs[w * 40 + v] - mx);
            lgs[w * 40 + 36] = mx;
            lgs[w * 40 + 37] = se;
            int tgt = x[b * T_ + s + 1];
            g_loss[b * TSTEPS + s] = (tgt == 0) ? 0.f : -lgs[w * 40 + tgt];
        }
        __syncwarp();
        for (int v = lane; v < V_; v += 32) {
            float pr = expf(lgs[w * 40 + v] - lgs[w * 40 + 36]) / lgs[w * 40 + 37];
            out[OFF_PROBS + ((size_t)b * TSTEPS + s) * V_ + v] = pr;
        }
    }
}

// ---------------- step kernel ----------------
// mode 0: gemm0(step 0), grid 64
// mode 1: grid 128 = gemm1(t)[0..63] + [gemm0(t+1) then fc(t-1)][64..127]
// mode 2: fc(126), grid 64
__global__ __launch_bounds__(512, 1) void step_kernel(int t, int mode,
        const int* __restrict__ x, const float* __restrict__ Wfc,
        const float* __restrict__ bfc, float* __restrict__ out) {
    extern __shared__ char sm[];
    int bid = blockIdx.x;
    if (mode == 0) { gemm_part(sm, bid, 0, 0, x); return; }
    if (mode == 2) { fc_part(sm, bid, 126, x, Wfc, bfc, out); return; }
    if (bid < 64) {
        gemm_part(sm, bid, 1, t, x);
    } else {
        if (t < 126) gemm_part(sm, bid - 64, 0, t + 1, x);
        if (t > 0) {
            __syncthreads();
            fc_part(sm, bid - 64, t - 1, x, Wfc, bfc, out);
        }
    }
}

// ---------------- prologue ----------------
__global__ void prep_kernel(const float* __restrict__ Wih0, const float* __restrict__ Whh0,
                            const float* __restrict__ Wih1, const float* __restrict__ Whh1,
                            const float* __restrict__ bi0, const float* __restrict__ bh0,
                            const float* __restrict__ bi1, const float* __restrict__ bh1,
                            const float* __restrict__ tab) {
    int i = blockIdx.x * 256 + threadIdx.x;
    if (i < 2048 * 1024) {
        int np = i >> 10, k = i & 1023;
        int r = ((np >> 3) & 3) * 512 + (np >> 5) * 8 + (np & 7);
        float v = (k < 512) ? Wih1[r * 512 + k] : Whh1[r * 512 + k - 512];
        g_W1[i] = __float2half(v);
    }
    if (i < 2048 * 640) {
        int np = i / 640, k = i - np * 640;
        int r = ((np >> 3) & 3) * 512 + (np >> 5) * 8 + (np & 7);
        float v = (k < 128) ? Wih0[r * 128 + k] : Whh0[r * 512 + k - 128];
        g_W0[i] = __float2half(v);
    }
    if (i < 36 * 128) {
        float v = tab[i];
        __half hi = __float2half(v);
        g_Eh[i] = hi;
        g_El[i] = __float2half(v - __half2float(hi));
    }
    if (i < 2048) {
        int r = ((i >> 3) & 3) * 512 + (i >> 5) * 8 + (i & 7);
        g_b0i[i] = bi0[r] + bh0[r];
        g_b1i[i] = bi1[r] + bh1[r];
    }
    if (i < 512 * 512) {
        g_c0[i] = 0.f; g_c1[i] = 0.f;
        __half z = __float2half(0.f);
        g_h0h[1][i] = z; g_h0l[1][i] = z;
        g_h1h[1][i] = z; g_h1l[1][i] = z;
    }
}

// ---------------- embedding output ----------------
__global__ void embed_kernel(const int* __restrict__ x, const float* __restrict__ tab,
                             float* __restrict__ out_emb) {
    int idx = blockIdx.x * 256 + threadIdx.x;
    if (idx >= (int)(EMB_N / 4)) return;
    int e4 = idx & 31;
    int bt = idx >> 5;
    int tok = x[bt];
    float4 v = reinterpret_cast<const float4*>(tab)[tok * 32 + e4];
    reinterpret_cast<float4*>(out_emb)[idx] = v;
}

// ---------------- finalize ----------------
__global__ void finalize_kernel(const int* __restrict__ x, float* __restrict__ out) {
    __shared__ float red[B_];
    int b = threadIdx.x;
    float s = 0.f;
    for (int t = 0; t < TSTEPS; t++) s += g_loss[b * TSTEPS + t];
    int len = 0;
    for (int t = 0; t < T_; t++) len += (x[b * T_ + t] != 0);
    float sl = s / (float)len;
    out[OFF_SL + b] = sl;
    red[b] = sl;
    __syncthreads();
    for (int st = 256; st > 0; st >>= 1) {
        if (b < st) red[b] += red[b + st];
        __syncthreads();
    }
    if (b == 0) out[OFF_MEAN] = red[0] / (float)B_;
}

// ---------------- launch ----------------
extern "C" void kernel_launch(void* const* d_in, const int* in_sizes, int n_in,
                              void* d_out, int out_size) {
    const int*   x    = (const int*)  d_in[0];
    const float* tab  = (const float*)d_in[1];
    const float* Wih0 = (const float*)d_in[2];
    const float* Whh0 = (const float*)d_in[3];
    const float* bih0 = (const float*)d_in[4];
    const float* bhh0 = (const float*)d_in[5];
    const float* Wih1 = (const float*)d_in[6];
    const float* Whh1 = (const float*)d_in[7];
    const float* bih1 = (const float*)d_in[8];
    const float* bhh1 = (const float*)d_in[9];
    const float* Wfc  = (const float*)d_in[10];
    const float* bfc  = (const float*)d_in[11];
    float* out = (float*)d_out;

    cudaFuncSetAttribute(step_kernel, cudaFuncAttributeMaxDynamicSharedMemorySize, SMEM_BYTES);

    prep_kernel<<<(2048 * 1024) / 256, 256>>>(Wih0, Whh0, Wih1, Whh1,
                                              bih0, bhh0, bih1, bhh1, tab);
    embed_kernel<<<(int)((EMB_N / 4 + 255) / 256), 256>>>(x, tab, out + OFF_EMB);

    step_kernel<<<64, 512, SMEM_BYTES>>>(0, 0, x, Wfc, bfc, out);
    for (int t = 0; t < TSTEPS; t++)
        step_kernel<<<128, 512, SMEM_BYTES>>>(t, 1, x, Wfc, bfc, out);
    step_kernel<<<64, 512, SMEM_BYTES>>>(0, 2, x, Wfc, bfc, out);
    finalize_kernel<<<1, B_>>>(x, out);
}

// round 16
// speedup vs baseline: 1.7104x; 1.3121x over previous
#include <cuda_runtime.h>
#include <cuda_fp16.h>
#include <math.h>
#include <stdint.h>

#define B_      512
#define T_      128
#define V_      36
#define E_      128
#define H_      512
#define TSTEPS  127

#define PROBS_N  ((size_t)B_ * TSTEPS * V_)
#define EMB_N    ((size_t)B_ * T_ * E_)
#define OFF_PROBS 0
#define OFF_EMB   (PROBS_N)
#define OFF_SL    (OFF_EMB + EMB_N)
#define OFF_MEAN  (OFF_SL + B_)

// ---------------- device scratch (no allocation) ----------------
// Weights: single fp16, gate-interleaved columns. out-col c <-> orig gate row
//   r = ((c>>3)&3)*512 + (c>>5)*8 + (c&7)
__device__ __half g_W0[2048 * 640];
__device__ __half g_W1[2048 * 1024];
__device__ float g_b0i[2048], g_b1i[2048];
__device__ __half g_E[36 * 128];                       // emb table, single fp16
__device__ __half g_h0[2][512 * 512];                  // h states, single fp16, parity-buffered
__device__ __half g_h1[2][512 * 512];
__device__ float g_c0[512 * 512], g_c1[512 * 512];
__device__ float g_loss[512 * TSTEPS];

// ---------------- smem layout (bytes) ----------------
// Per stage: 2 tiles [128 rows][64 k] fp16 (A, B), row stride 72 elems
#define LDA2     72
#define TILE_B2  (128 * LDA2 * 2)            // 18432
#define S_A      0
#define S_B      (1 * TILE_B2)
#define STAGE_B  (2 * TILE_B2)               // 36864
#define NSTAGE   3
#define S_TOK    (NSTAGE * STAGE_B)          // 110592
#define SMEM_BYTES (S_TOK + 512)             // 111104

// ---------------- PTX helpers ----------------
__device__ __forceinline__ uint32_t smem_u32(const void* p) {
    uint32_t a;
    asm("{ .reg .u64 t; cvta.to.shared.u64 t, %1; cvt.u32.u64 %0, t; }" : "=r"(a) : "l"(p));
    return a;
}
__device__ __forceinline__ void cp16(uint32_t dst, const void* src) {
    asm volatile("cp.async.cg.shared.global [%0], [%1], 16;" :: "r"(dst), "l"(src));
}
__device__ __forceinline__ void cp_commit() { asm volatile("cp.async.commit_group;" ::: "memory"); }
__device__ __forceinline__ void cp_wait0()  { asm volatile("cp.async.wait_group 0;" ::: "memory"); }
__device__ __forceinline__ void cp_wait1()  { asm volatile("cp.async.wait_group 1;" ::: "memory"); }
__device__ __forceinline__ void ldsm_x4(uint32_t* r, uint32_t addr) {
    asm volatile("ldmatrix.sync.aligned.m8n8.x4.shared.b16 {%0,%1,%2,%3}, [%4];"
                 : "=r"(r[0]), "=r"(r[1]), "=r"(r[2]), "=r"(r[3]) : "r"(addr));
}
__device__ __forceinline__ void mma16816(float* d, const uint32_t* a, const uint32_t* b) {
    asm volatile(
        "mma.sync.aligned.m16n8k16.row.col.f32.f16.f16.f32 "
        "{%0,%1,%2,%3}, {%4,%5,%6,%7}, {%8,%9}, {%0,%1,%2,%3};"
        : "+f"(d[0]), "+f"(d[1]), "+f"(d[2]), "+f"(d[3])
        : "r"(a[0]), "r"(a[1]), "r"(a[2]), "r"(a[3]), "r"(b[0]), "r"(b[1]));
}

// ---------------- GEMM + fused LSTM cell (512 thr, 16 warps 4x4, warp tile 32x32, BK=64) ----
// which==0: step s: A = [emb(x[:,s]) | h0[par_prev]], K=640,  writes h0[par_cur], c0
// which==1: step s: A = [h0[par_cur] | h1[par_prev]], K=1024, writes h1[par_cur], c1
__device__ void gemm_part(char* sm, int tileid, int which, int s, const int* __restrict__ x) {
    const int tid = threadIdx.x;
    const int m0 = (tileid >> 4) * 128;
    const int col0 = (tileid & 15) * 128;
    const int K = which ? 1024 : 640;
    const int nch = K / 64;
    const int par_cur = s & 1, par_prev = (s + 1) & 1;
    const uint32_t sb = smem_u32(sm);

    int* tok_s = (int*)(sm + S_TOK);
    if (which == 0 && tid < 128) tok_s[tid] = x[(m0 + tid) * T_ + s];
    __syncthreads();

    const __half* __restrict__ W = which ? g_W1 : g_W0;

    const int warp = tid >> 5, lane = tid & 31;
    const int wm = warp >> 2, wn = warp & 3;

    // loader: 512 threads cover 64 rows x 64 k per pass; 2 passes = 128 rows
    const int ldr = (tid >> 3);          // 0..63
    const int ldk = (tid & 7) * 8;       // 0..56

    auto load_chunk = [&](int c, int buf) {
        const int kb = c * 64;
        const uint32_t sbst = sb + buf * STAGE_B;
#pragma unroll
        for (int it = 0; it < 2; it++) {
            const int r = it * 64 + ldr;
            const int kk = kb + ldk;
            const __half* pa;
            if (which) {
                if (kb < 512) pa = &g_h0[par_cur][(size_t)(m0 + r) * 512 + kk];
                else          pa = &g_h1[par_prev][(size_t)(m0 + r) * 512 + kk - 512];
            } else {
                if (kb < 128) pa = &g_E[(size_t)tok_s[r] * 128 + kk];
                else          pa = &g_h0[par_prev][(size_t)(m0 + r) * 512 + kk - 128];
            }
            const int dst = (r * LDA2 + ldk) * 2;
            cp16(sbst + S_A + dst, pa);
            size_t bo = (size_t)(col0 + r) * K + kk;
            cp16(sbst + S_B + dst, &W[bo]);
        }
    };

    float acc[2][4][4];
#pragma unroll
    for (int i = 0; i < 2; i++)
#pragma unroll
        for (int q = 0; q < 4; q++)
#pragma unroll
            for (int r = 0; r < 4; r++) acc[i][q][r] = 0.f;

    // ldmatrix per-thread base addresses (stage 0)
    const int arow = wm * 32 + (lane & 15);
    const int ahalf = (lane >> 4) * 8;                 // A: x4 = 2 m-halves x 2 k-halves
    const uint32_t a_0 = sb + S_A + (arow * LDA2 + ahalf) * 2;
    const int brow = wn * 32 + (lane & 7);
    const int bhalf = (lane >> 3) * 8;                 // B: x4 = 4 consecutive k-halves
    const uint32_t b_0 = sb + S_B + (brow * LDA2 + bhalf) * 2;

    // prologue: 2 chunks in flight
    load_chunk(0, 0); cp_commit();
    load_chunk(1, 1); cp_commit();

    int buf = 0;
    for (int c = 0; c < nch; c++) {
        if (c + 1 < nch) cp_wait1(); else cp_wait0();
        // single barrier: all warps done READING stage (c+2)%NSTAGE before overwrite
        __syncthreads();
        if (c + 2 < nch) {
            int nb = buf + 2; if (nb >= NSTAGE) nb -= NSTAGE;
            load_chunk(c + 2, nb);
            cp_commit();
        }
        const uint32_t so = (uint32_t)(buf * STAGE_B);
#pragma unroll
        for (int kh = 0; kh < 2; kh++) {
            const uint32_t koff = so + (uint32_t)(kh * 32 * 2);   // 32 k-elements per half
            uint32_t bfr[4][4], af[2][2][4];
            // load B + A fragments
#pragma unroll
            for (int q = 0; q < 4; q++)
                ldsm_x4(bfr[q], b_0 + koff + q * (8 * LDA2 * 2));
#pragma unroll
            for (int ks = 0; ks < 2; ks++)
#pragma unroll
                for (int mf = 0; mf < 2; mf++)
                    ldsm_x4(af[ks][mf], a_0 + koff + ks * 32 + mf * (16 * LDA2 * 2));
            // single pass: a * b  (8 independent acc chains per ks)
#pragma unroll
            for (int ks = 0; ks < 2; ks++)
#pragma unroll
                for (int mf = 0; mf < 2; mf++)
#pragma unroll
                    for (int q = 0; q < 4; q++)
                        mma16816(acc[mf][q], af[ks][mf], &bfr[q][ks * 2]);
        }
        if (++buf == NSTAGE) buf = 0;
    }

    // ---- fused LSTM cell epilogue ----
    const float* __restrict__ bias = which ? g_b1i : g_b0i;
    float* __restrict__ Cc = which ? g_c1 : g_c0;
    __half* __restrict__ Hc = which ? g_h1[par_cur] : g_h0[par_cur];

    const int p = lane & 3;
    const int rowb = lane >> 2;
    const int jbase = (col0 >> 2) + wn * 8;
    float bi[4][2];
#pragma unroll
    for (int g = 0; g < 4; g++) {
        bi[g][0] = bias[col0 + wn * 32 + g * 8 + 2 * p + 0];
        bi[g][1] = bias[col0 + wn * 32 + g * 8 + 2 * p + 1];
    }

#pragma unroll
    for (int mf = 0; mf < 2; mf++) {
#pragma unroll
        for (int r2 = 0; r2 < 2; r2++) {
            const int m = m0 + wm * 32 + mf * 16 + rowb + r2 * 8;
            const size_t cb = (size_t)m * 512 + jbase + 2 * p;
            float2 cold = *(const float2*)&Cc[cb];
            float hn[2], cn[2];
#pragma unroll
            for (int bit = 0; bit < 2; bit++) {
                const int ri = r2 * 2 + bit;
                float iv = acc[mf][0][ri] + bi[0][bit];
                float fv = acc[mf][1][ri] + bi[1][bit];
                float gv = acc[mf][2][ri] + bi[2][bit];
                float ov = acc[mf][3][ri] + bi[3][bit];
                float si = 1.f / (1.f + expf(-iv));
                float sf = 1.f / (1.f + expf(-fv));
                float tg = tanhf(gv);
                float so = 1.f / (1.f + expf(-ov));
                float co = bit ? cold.y : cold.x;
                cn[bit] = sf * co + si * tg;
                hn[bit] = so * tanhf(cn[bit]);
            }
            *(float2*)&Cc[cb] = make_float2(cn[0], cn[1]);
            __half h0b = __float2half(hn[0]);
            __half h1b = __float2half(hn[1]);
            uint32_t hp = (uint32_t)__half_as_ushort(h0b) |
                          ((uint32_t)__half_as_ushort(h1b) << 16);
            *(uint32_t*)&Hc[cb] = hp;
        }
    }
}

// ---------------- fc: 8 batches/block, warp w<8 handles batch b0+w ----------------
__device__ void fc_part(char* sm, int fid, int s, const int* __restrict__ x,
                        const float* __restrict__ Wfc, const float* __restrict__ bfc,
                        float* __restrict__ out) {
    const int tid = threadIdx.x;
    float* hs = (float*)sm;               // [8][512]
    float* lgs = (float*)(sm + 16384);    // [8][40]
    const int b0 = fid * 8;
    const int par = s & 1;
    for (int i = tid; i < 8 * 512; i += 512) {
        int b = i >> 9, k = i & 511;
        hs[i] = __half2float(g_h1[par][(size_t)(b0 + b) * 512 + k]);
    }
    __syncthreads();
    const int w = tid >> 5, lane = tid & 31;
    if (w < 8) {
        const int b = b0 + w;
        const float* hb = hs + w * 512;
        for (int v = 0; v < V_; v++) {
            float sum = 0.f;
#pragma unroll
            for (int kk = 0; kk < 16; kk++) {
                int k = lane + kk * 32;
                sum += hb[k] * Wfc[v * 512 + k];
            }
#pragma unroll
            for (int o = 16; o; o >>= 1) sum += __shfl_xor_sync(0xffffffffu, sum, o);
            if (lane == 0) lgs[w * 40 + v] = fmaxf(sum + bfc[v], 0.f);
        }
        __syncwarp();
        if (lane == 0) {
            float mx = -1e30f;
            for (int v = 0; v < V_; v++) mx = fmaxf(mx, lgs[w * 40 + v]);
            float se = 0.f;
            for (int v = 0; v < V_; v++) se += expf(lgs[w * 40 + v] - mx);
            lgs[w * 40 + 36] = mx;
            lgs[w * 40 + 37] = se;
            int tgt = x[b * T_ + s + 1];
            g_loss[b * TSTEPS + s] = (tgt == 0) ? 0.f : -lgs[w * 40 + tgt];
        }
        __syncwarp();
        for (int v = lane; v < V_; v += 32) {
            float pr = expf(lgs[w * 40 + v] - lgs[w * 40 + 36]) / lgs[w * 40 + 37];
            out[OFF_PROBS + ((size_t)b * TSTEPS + s) * V_ + v] = pr;
        }
    }
}

// ---------------- step kernel ----------------
// mode 0: gemm0(step 0), grid 64
// mode 1: grid 128 = gemm1(t)[0..63] + [gemm0(t+1) then fc(t-1)][64..127]
// mode 2: fc(126), grid 64
__global__ __launch_bounds__(512, 1) void step_kernel(int t, int mode,
        const int* __restrict__ x, const float* __restrict__ Wfc,
        const float* __restrict__ bfc, float* __restrict__ out) {
    extern __shared__ char sm[];
    int bid = blockIdx.x;
    if (mode == 0) { gemm_part(sm, bid, 0, 0, x); return; }
    if (mode == 2) { fc_part(sm, bid, 126, x, Wfc, bfc, out); return; }
    if (bid < 64) {
        gemm_part(sm, bid, 1, t, x);
    } else {
        if (t < 126) gemm_part(sm, bid - 64, 0, t + 1, x);
        if (t > 0) {
            __syncthreads();
            fc_part(sm, bid - 64, t - 1, x, Wfc, bfc, out);
        }
    }
}

// ---------------- prologue ----------------
__global__ void prep_kernel(const float* __restrict__ Wih0, const float* __restrict__ Whh0,
                            const float* __restrict__ Wih1, const float* __restrict__ Whh1,
                            const float* __restrict__ bi0, const float* __restrict__ bh0,
                            const float* __restrict__ bi1, const float* __restrict__ bh1,
                            const float* __restrict__ tab) {
    int i = blockIdx.x * 256 + threadIdx.x;
    if (i < 2048 * 1024) {
        int np = i >> 10, k = i & 1023;
        int r = ((np >> 3) & 3) * 512 + (np >> 5) * 8 + (np & 7);
        float v = (k < 512) ? Wih1[r * 512 + k] : Whh1[r * 512 + k - 512];
        g_W1[i] = __float2half(v);
    }
    if (i < 2048 * 640) {
        int np = i / 640, k = i - np * 640;
        int r = ((np >> 3) & 3) * 512 + (np >> 5) * 8 + (np & 7);
        float v = (k < 128) ? Wih0[r * 128 + k] : Whh0[r * 512 + k - 128];
        g_W0[i] = __float2half(v);
    }
    if (i < 36 * 128) {
        g_E[i] = __float2half(tab[i]);
    }
    if (i < 2048) {
        int r = ((i >> 3) & 3) * 512 + (i >> 5) * 8 + (i & 7);
        g_b0i[i] = bi0[r] + bh0[r];
        g_b1i[i] = bi1[r] + bh1[r];
    }
    if (i < 512 * 512) {
        g_c0[i] = 0.f; g_c1[i] = 0.f;
        __half z = __float2half(0.f);
        g_h0[1][i] = z;
        g_h1[1][i] = z;
    }
}

// ---------------- embedding output ----------------
__global__ void embed_kernel(const int* __restrict__ x, const float* __restrict__ tab,
                             float* __restrict__ out_emb) {
    int idx = blockIdx.x * 256 + threadIdx.x;
    if (idx >= (int)(EMB_N / 4)) return;
    int e4 = idx & 31;
    int bt = idx >> 5;
    int tok = x[bt];
    float4 v = reinterpret_cast<const float4*>(tab)[tok * 32 + e4];
    reinterpret_cast<float4*>(out_emb)[idx] = v;
}

// ---------------- finalize ----------------
__global__ void finalize_kernel(const int* __restrict__ x, float* __restrict__ out) {
    __shared__ float red[B_];
    int b = threadIdx.x;
    float s = 0.f;
    for (int t = 0; t < TSTEPS; t++) s += g_loss[b * TSTEPS + t];
    int len = 0;
    for (int t = 0; t < T_; t++) len += (x[b * T_ + t] != 0);
    float sl = s / (float)len;
    out[OFF_SL + b] = sl;
    red[b] = sl;
    __syncthreads();
    for (int st = 256; st > 0; st >>= 1) {
        if (b < st) red[b] += red[b + st];
        __syncthreads();
    }
    if (b == 0) out[OFF_MEAN] = red[0] / (float)B_;
}

// ---------------- launch ----------------
extern "C" void kernel_launch(void* const* d_in, const int* in_sizes, int n_in,
                              void* d_out, int out_size) {
    const int*   x    = (const int*)  d_in[0];
    const float* tab  = (const float*)d_in[1];
    const float* Wih0 = (const float*)d_in[2];
    const float* Whh0 = (const float*)d_in[3];
    const float* bih0 = (const float*)d_in[4];
    const float* bhh0 = (const float*)d_in[5];
    const float* Wih1 = (const float*)d_in[6];
    const float* Whh1 = (const float*)d_in[7];
    const float* bih1 = (const float*)d_in[8];
    const float* bhh1 = (const float*)d_in[9];
    const float* Wfc  = (const float*)d_in[10];
    const float* bfc  = (const float*)d_in[11];
    float* out = (float*)d_out;

    cudaFuncSetAttribute(step_kernel, cudaFuncAttributeMaxDynamicSharedMemorySize, SMEM_BYTES);

    prep_kernel<<<(2048 * 1024) / 256, 256>>>(Wih0, Whh0, Wih1, Whh1,
                                              bih0, bhh0, bih1, bhh1, tab);
    embed_kernel<<<(int)((EMB_N / 4 + 255) / 256), 256>>>(x, tab, out + OFF_EMB);

    step_kernel<<<64, 512, SMEM_BYTES>>>(0, 0, x, Wfc, bfc, out);
    for (int t = 0; t < TSTEPS; t++)
        step_kernel<<<128, 512, SMEM_BYTES>>>(t, 1, x, Wfc, bfc, out);
    step_kernel<<<64, 512, SMEM_BYTES>>>(0, 2, x, Wfc, bfc, out);
    finalize_kernel<<<1, B_>>>(x, out);
}